// round 1
// baseline (speedup 1.0000x reference)
#include <cuda_runtime.h>
#include <cuda_bf16.h>
#include <math.h>

// Problem constants
#define BATCH 2
#define SEQ 2048
#define DMODEL 2048
#define NHEADS 16
#define NKV 8
#define HD 128
#define ROWS (BATCH*SEQ)          // 4096
#define QDIM (NHEADS*HD)          // 2048
#define KVDIM (NKV*HD)            // 1024

// Scratch (device globals: allocation-free per harness rules)
__device__ float g_Q[(size_t)ROWS * QDIM];    // 32MB  [b,s,h,hd]
__device__ float g_K[(size_t)ROWS * KVDIM];   // 16MB  [b,s,kvh,hd]
__device__ float g_V[(size_t)ROWS * KVDIM];   // 16MB
__device__ float g_O[(size_t)ROWS * QDIM];    // 32MB  attention out [b,s,h,hd]

// ---------------------------------------------------------------------------
// SGEMM: C[m][n] = sum_k A[m*K+k] * B[n*K+k]   (both K-major, "NT" form)
// BM=BN=128, BK=16, 256 threads, 8x8 register tile.
// ---------------------------------------------------------------------------
__global__ __launch_bounds__(256)
void sgemm_nt(const float* __restrict__ A, const float* __restrict__ B,
              float* __restrict__ C, int M, int N, int K)
{
    __shared__ float As[16 * 128];  // [k][m]
    __shared__ float Bs[16 * 128];  // [k][n]

    const int tid = threadIdx.x;
    const int bm = blockIdx.y * 128;
    const int bn = blockIdx.x * 128;
    const int tx = tid & 15;
    const int ty = tid >> 4;

    float acc[8][8];
#pragma unroll
    for (int i = 0; i < 8; i++)
#pragma unroll
        for (int j = 0; j < 8; j++) acc[i][j] = 0.f;

    for (int k0 = 0; k0 < K; k0 += 16) {
#pragma unroll
        for (int t = 0; t < 2; t++) {
            int idx = tid + t * 256;          // 0..511
            int row = idx >> 2;               // 0..127
            int kq  = (idx & 3) * 4;          // 0,4,8,12
            float4 va = *(const float4*)&A[(size_t)(bm + row) * K + k0 + kq];
            As[(kq + 0) * 128 + row] = va.x;
            As[(kq + 1) * 128 + row] = va.y;
            As[(kq + 2) * 128 + row] = va.z;
            As[(kq + 3) * 128 + row] = va.w;
            float4 vb = *(const float4*)&B[(size_t)(bn + row) * K + k0 + kq];
            Bs[(kq + 0) * 128 + row] = vb.x;
            Bs[(kq + 1) * 128 + row] = vb.y;
            Bs[(kq + 2) * 128 + row] = vb.z;
            Bs[(kq + 3) * 128 + row] = vb.w;
        }
        __syncthreads();

#pragma unroll
        for (int k = 0; k < 16; k++) {
            float a[8], b[8];
#pragma unroll
            for (int i = 0; i < 8; i++) a[i] = As[k * 128 + ty * 8 + i];
#pragma unroll
            for (int j = 0; j < 8; j++) b[j] = Bs[k * 128 + tx * 8 + j];
#pragma unroll
            for (int i = 0; i < 8; i++)
#pragma unroll
                for (int j = 0; j < 8; j++)
                    acc[i][j] += a[i] * b[j];
        }
        __syncthreads();
    }

#pragma unroll
    for (int i = 0; i < 8; i++) {
        size_t crow = (size_t)(bm + ty * 8 + i) * N + bn + tx * 8;
        float4 v0 = make_float4(acc[i][0], acc[i][1], acc[i][2], acc[i][3]);
        float4 v1 = make_float4(acc[i][4], acc[i][5], acc[i][6], acc[i][7]);
        *(float4*)&C[crow]     = v0;
        *(float4*)&C[crow + 4] = v1;
    }
}

// ---------------------------------------------------------------------------
// RoPE (Gemma2 style, half rotation). fp64 angle math for accuracy.
// q layout: [row(b*s)][n_heads][128]. pos = row % SEQ.
// ---------------------------------------------------------------------------
__global__ void rope_kernel(float* __restrict__ q, int n_heads, int total)
{
    int t = blockIdx.x * blockDim.x + threadIdx.x;
    if (t >= total) return;
    const int pairs_per_row = n_heads * 64;
    int row = t / pairs_per_row;
    int p = t - row * pairs_per_row;
    int head = p >> 6;
    int j = p & 63;
    int pos = row & (SEQ - 1);

    // inv_freq = 10000^(-j/64); angle = pos * inv_freq
    double inv = exp2(-(double)j * (13.287712379549449 / 64.0));
    double ang = (double)pos * inv;
    double sd, cd;
    sincos(ang, &sd, &cd);
    float sn = (float)sd, cs = (float)cd;

    size_t base = (size_t)row * (pairs_per_row * 2) + (size_t)head * 128 + j;
    float a = q[base];
    float b = q[base + 64];
    q[base]      = a * cs - b * sn;
    q[base + 64] = b * cs + a * sn;
}

// ---------------------------------------------------------------------------
// Softcap 50*tanh(s/50) via Taylor (|s/50| << 1 for this data); MUFU-free on
// the hot path, accurate fallback for large args.
// ---------------------------------------------------------------------------
__device__ __forceinline__ float softcap50(float s)
{
    float x = s * 0.02f;
    float x2 = x * x;
    if (fabsf(x) < 0.39f) {
        // tanh(x) = x(1 - x^2/3 + 2x^4/15 - 17x^6/315)
        float t = x * (1.0f + x2 * (-0.333333343f + x2 * (0.133333340f + x2 * (-0.0539682545f))));
        return 50.0f * t;
    }
    return 50.0f * tanhf(x);
}

#define NEG_BIG (-1.0e30f)

// ---------------------------------------------------------------------------
// Flash attention, fp32, causal, online softmax.
// Block: 256 threads. Tile BM=64 q-rows x BN=64 k-rows, HD=128.
// grid = (32 qtiles, 16 heads, 2 batch).
// smem: sQT[128][64] | sKV (KT[128][64] / V[64][128]) | sP[64][64] = 80KB dyn.
// Thread map: tx=tid&15, ty=tid>>4. S micro-tile 4x4; O micro-tile 4 rows x 8 dims.
// ---------------------------------------------------------------------------
__global__ __launch_bounds__(256)
void attn_kernel(const float* __restrict__ Q, const float* __restrict__ K,
                 const float* __restrict__ V, float* __restrict__ O)
{
    extern __shared__ float smem[];
    float* sQT = smem;                 // [k][row]  128x64
    float* sKV = smem + 128 * 64;      // KT: [k][col] 128x64   OR   V: [row][d] 64x128
    float* sP  = smem + 2 * 128 * 64;  // [row][col] 64x64

    const int qt = blockIdx.x;
    const int h  = blockIdx.y;
    const int b  = blockIdx.z;
    const int kvh = h >> 1;            // repeat_kv with N_REP=2
    const int tid = threadIdx.x;
    const int tx = tid & 15;
    const int ty = tid >> 4;

    const int q0 = qt * 64;
    const size_t qhead = (size_t)b * SEQ * QDIM + (size_t)h * HD;
    const size_t khead = (size_t)b * SEQ * KVDIM + (size_t)kvh * HD;

    const float scale = 0.08838834764831845f;  // 128^-0.5

    // Load Q tile, transposed + pre-scaled
#pragma unroll
    for (int t = 0; t < 8; t++) {
        int idx = tid + t * 256;       // 0..2047 (64 rows x 32 float4)
        int row = idx >> 5;
        int kq = (idx & 31) * 4;
        float4 v = *(const float4*)&Q[qhead + (size_t)(q0 + row) * QDIM + kq];
        sQT[(kq + 0) * 64 + row] = v.x * scale;
        sQT[(kq + 1) * 64 + row] = v.y * scale;
        sQT[(kq + 2) * 64 + row] = v.z * scale;
        sQT[(kq + 3) * 64 + row] = v.w * scale;
    }

    float m_i[4], l_i[4], acc[4][8];
#pragma unroll
    for (int i = 0; i < 4; i++) {
        m_i[i] = NEG_BIG; l_i[i] = 0.f;
#pragma unroll
        for (int j = 0; j < 8; j++) acc[i][j] = 0.f;
    }

    for (int kt = 0; kt <= qt; kt++) {
        const int k0 = kt * 64;
        __syncthreads();  // prior-iter sKV/sP readers done; Q tile visible (iter 0)

        // Load K tile transposed
#pragma unroll
        for (int t = 0; t < 8; t++) {
            int idx = tid + t * 256;
            int row = idx >> 5;
            int kq = (idx & 31) * 4;
            float4 v = *(const float4*)&K[khead + (size_t)(k0 + row) * KVDIM + kq];
            sKV[(kq + 0) * 64 + row] = v.x;
            sKV[(kq + 1) * 64 + row] = v.y;
            sKV[(kq + 2) * 64 + row] = v.z;
            sKV[(kq + 3) * 64 + row] = v.w;
        }
        __syncthreads();

        // S = (Q*scale) @ K^T   (4x4 per thread)
        float S[4][4];
#pragma unroll
        for (int i = 0; i < 4; i++)
#pragma unroll
            for (int j = 0; j < 4; j++) S[i][j] = 0.f;

#pragma unroll 4
        for (int k = 0; k < 128; k++) {
            float a[4], bb[4];
#pragma unroll
            for (int i = 0; i < 4; i++) a[i]  = sQT[k * 64 + ty * 4 + i];
#pragma unroll
            for (int j = 0; j < 4; j++) bb[j] = sKV[k * 64 + tx * 4 + j];
#pragma unroll
            for (int i = 0; i < 4; i++)
#pragma unroll
                for (int j = 0; j < 4; j++)
                    S[i][j] += a[i] * bb[j];
        }

        // softcap + causal mask + online softmax update
        const bool diag = (kt == qt);
#pragma unroll
        for (int i = 0; i < 4; i++) {
            const int qrow = q0 + ty * 4 + i;
#pragma unroll
            for (int j = 0; j < 4; j++) {
                float s = softcap50(S[i][j]);
                if (diag && (k0 + tx * 4 + j) > qrow) s = NEG_BIG;
                S[i][j] = s;
            }
            float mx = fmaxf(fmaxf(S[i][0], S[i][1]), fmaxf(S[i][2], S[i][3]));
#pragma unroll
            for (int off = 1; off < 16; off <<= 1)
                mx = fmaxf(mx, __shfl_xor_sync(0xffffffffu, mx, off));

            float m_new = fmaxf(m_i[i], mx);
            float corr = (m_i[i] < -1e29f) ? 0.f : __expf(m_i[i] - m_new);
            float rs = 0.f;
#pragma unroll
            for (int j = 0; j < 4; j++) {
                float p = (S[i][j] < -1e29f) ? 0.f : __expf(S[i][j] - m_new);
                S[i][j] = p;
                rs += p;
            }
#pragma unroll
            for (int off = 1; off < 16; off <<= 1)
                rs += __shfl_xor_sync(0xffffffffu, rs, off);

            l_i[i] = l_i[i] * corr + rs;
            m_i[i] = m_new;
#pragma unroll
            for (int j = 0; j < 8; j++) acc[i][j] *= corr;
        }

        // stash P
#pragma unroll
        for (int i = 0; i < 4; i++)
#pragma unroll
            for (int j = 0; j < 4; j++)
                sP[(ty * 4 + i) * 64 + tx * 4 + j] = S[i][j];
        __syncthreads();  // K reads done, P written

        // Load V tile, natural layout [row][d]
#pragma unroll
        for (int t = 0; t < 8; t++) {
            int idx = tid + t * 256;
            int row = idx >> 5;
            int kq = (idx & 31) * 4;
            float4 v = *(const float4*)&V[khead + (size_t)(k0 + row) * KVDIM + kq];
            *(float4*)&sKV[row * 128 + kq] = v;
        }
        __syncthreads();

        // O += P @ V  (4 rows x 8 dims per thread)
#pragma unroll 2
        for (int jj = 0; jj < 64; jj++) {
            float p[4], v[8];
#pragma unroll
            for (int i = 0; i < 4; i++) p[i] = sP[(ty * 4 + i) * 64 + jj];
#pragma unroll
            for (int j = 0; j < 8; j++) v[j] = sKV[jj * 128 + tx * 8 + j];
#pragma unroll
            for (int i = 0; i < 4; i++)
#pragma unroll
                for (int j = 0; j < 8; j++)
                    acc[i][j] += p[i] * v[j];
        }
    }

    // epilogue: normalize + store to [b,s,h,hd]
#pragma unroll
    for (int i = 0; i < 4; i++) {
        float inv = 1.0f / l_i[i];
        int row = q0 + ty * 4 + i;
        size_t obase = ((size_t)b * SEQ + row) * QDIM + (size_t)h * HD + tx * 8;
#pragma unroll
        for (int j = 0; j < 8; j++) acc[i][j] *= inv;
        float4 v0 = make_float4(acc[i][0], acc[i][1], acc[i][2], acc[i][3]);
        float4 v1 = make_float4(acc[i][4], acc[i][5], acc[i][6], acc[i][7]);
        *(float4*)&O[obase]     = v0;
        *(float4*)&O[obase + 4] = v1;
    }
}

// ---------------------------------------------------------------------------
extern "C" void kernel_launch(void* const* d_in, const int* in_sizes, int n_in,
                              void* d_out, int out_size)
{
    const float* x  = (const float*)d_in[0];
    const float* wq = (const float*)d_in[1];
    const float* wk = (const float*)d_in[2];
    const float* wv = (const float*)d_in[3];
    const float* wo = (const float*)d_in[4];
    float* out = (float*)d_out;

    float *Qp, *Kp, *Vp, *Op;
    cudaGetSymbolAddress((void**)&Qp, g_Q);
    cudaGetSymbolAddress((void**)&Kp, g_K);
    cudaGetSymbolAddress((void**)&Vp, g_V);
    cudaGetSymbolAddress((void**)&Op, g_O);

    // QKV projections
    sgemm_nt<<<dim3(QDIM / 128, ROWS / 128), 256>>>(x, wq, Qp, ROWS, QDIM, DMODEL);
    sgemm_nt<<<dim3(KVDIM / 128, ROWS / 128), 256>>>(x, wk, Kp, ROWS, KVDIM, DMODEL);
    sgemm_nt<<<dim3(KVDIM / 128, ROWS / 128), 256>>>(x, wv, Vp, ROWS, KVDIM, DMODEL);

    // RoPE on Q and K
    {
        int totq = ROWS * NHEADS * 64;
        int totk = ROWS * NKV * 64;
        rope_kernel<<<(totq + 255) / 256, 256>>>(Qp, NHEADS, totq);
        rope_kernel<<<(totk + 255) / 256, 256>>>(Kp, NKV, totk);
    }

    // Attention
    {
        static const int SMEM = (128 * 64 + 128 * 64 + 64 * 64) * 4;  // 80KB
        cudaFuncSetAttribute(attn_kernel, cudaFuncAttributeMaxDynamicSharedMemorySize, SMEM);
        attn_kernel<<<dim3(SEQ / 64, NHEADS, BATCH), 256, SMEM>>>(Qp, Kp, Vp, Op);
    }

    // Output projection
    sgemm_nt<<<dim3(DMODEL / 128, ROWS / 128), 256>>>(Op, wo, out, ROWS, DMODEL, DMODEL);
}

// round 2
// speedup vs baseline: 1.6974x; 1.6974x over previous
#include <cuda_runtime.h>
#include <cuda_bf16.h>
#include <math.h>
#include <stdint.h>

// Problem constants
#define BATCH 2
#define SEQ 2048
#define DMODEL 2048
#define NHEADS 16
#define NKV 8
#define HD 128
#define ROWS (BATCH*SEQ)          // 4096
#define QDIM (NHEADS*HD)          // 2048
#define KVDIM (NKV*HD)            // 1024

// fp32 scratch
__device__ float g_Q[(size_t)ROWS * QDIM];
__device__ float g_K[(size_t)ROWS * KVDIM];
__device__ float g_V[(size_t)ROWS * KVDIM];
__device__ float g_O[(size_t)ROWS * QDIM];

// bf16 split scratch (hi / lo)
__device__ __nv_bfloat16 g_xh[(size_t)ROWS * DMODEL],  g_xl[(size_t)ROWS * DMODEL];
__device__ __nv_bfloat16 g_wqh[(size_t)QDIM * DMODEL], g_wql[(size_t)QDIM * DMODEL];
__device__ __nv_bfloat16 g_wkh[(size_t)KVDIM * DMODEL], g_wkl[(size_t)KVDIM * DMODEL];
__device__ __nv_bfloat16 g_wvh[(size_t)KVDIM * DMODEL], g_wvl[(size_t)KVDIM * DMODEL];
__device__ __nv_bfloat16 g_woh[(size_t)DMODEL * QDIM], g_wol[(size_t)DMODEL * QDIM];
__device__ __nv_bfloat16 g_oh[(size_t)ROWS * QDIM],   g_ol[(size_t)ROWS * QDIM];

// rope table: [pos][j] -> (cos, sin)
__device__ float g_rope[SEQ * 64 * 2];

// ---------------------------------------------------------------------------
// fp32 -> bf16 hi/lo split (vectorized x4)
// ---------------------------------------------------------------------------
__global__ void split4_kernel(const float4* __restrict__ src,
                              __nv_bfloat162* __restrict__ hi,
                              __nv_bfloat162* __restrict__ lo, int n4)
{
    int i = blockIdx.x * blockDim.x + threadIdx.x;
    if (i >= n4) return;
    float4 v = src[i];
    __nv_bfloat16 h0 = __float2bfloat16(v.x);
    __nv_bfloat16 h1 = __float2bfloat16(v.y);
    __nv_bfloat16 h2 = __float2bfloat16(v.z);
    __nv_bfloat16 h3 = __float2bfloat16(v.w);
    __nv_bfloat16 l0 = __float2bfloat16(v.x - __bfloat162float(h0));
    __nv_bfloat16 l1 = __float2bfloat16(v.y - __bfloat162float(h1));
    __nv_bfloat16 l2 = __float2bfloat16(v.z - __bfloat162float(h2));
    __nv_bfloat16 l3 = __float2bfloat16(v.w - __bfloat162float(h3));
    hi[i * 2]     = __nv_bfloat162(h0, h1);
    hi[i * 2 + 1] = __nv_bfloat162(h2, h3);
    lo[i * 2]     = __nv_bfloat162(l0, l1);
    lo[i * 2 + 1] = __nv_bfloat162(l2, l3);
}

// ---------------------------------------------------------------------------
// RoPE table (fp64, tiny) + apply (fp32, memory-bound)
// ---------------------------------------------------------------------------
__global__ void rope_table_kernel(float* __restrict__ tab)
{
    int i = blockIdx.x * blockDim.x + threadIdx.x;   // 0..131071
    if (i >= SEQ * 64) return;
    int pos = i >> 6, j = i & 63;
    double inv = exp2(-(double)j * (13.287712379549449 / 64.0));
    double sd, cd;
    sincos((double)pos * inv, &sd, &cd);
    tab[i * 2]     = (float)cd;
    tab[i * 2 + 1] = (float)sd;
}

__global__ void rope_apply_kernel(float* __restrict__ q, const float* __restrict__ tab,
                                  int n_heads, int total)
{
    int t = blockIdx.x * blockDim.x + threadIdx.x;
    if (t >= total) return;
    const int pairs_per_row = n_heads * 64;
    int row = t / pairs_per_row;
    int p = t - row * pairs_per_row;
    int head = p >> 6;
    int j = p & 63;
    int pos = row & (SEQ - 1);

    float cs = tab[(pos * 64 + j) * 2];
    float sn = tab[(pos * 64 + j) * 2 + 1];

    size_t base = (size_t)row * (pairs_per_row * 2) + (size_t)head * 128 + j;
    float a = q[base];
    float b = q[base + 64];
    q[base]      = a * cs - b * sn;
    q[base + 64] = b * cs + a * sn;
}

// ---------------------------------------------------------------------------
// bf16x3-split GEMM on tensor cores (mma.sync m16n8k16).
// C[m][n] = sum_k A[m][k]*B[n][k], A=(Ah+Al), B=(Bh+Bl), fp32 accum.
// BM=BN=128, BK=32, 256 threads (8 warps, 2x4), warp tile 64x32.
// smem row stride 40 bf16 (80B) -> conflict-free ldmatrix.
// ---------------------------------------------------------------------------
#define GBM 128
#define GBN 128
#define GBK 32
#define ASTR 40
#define GTILE (128 * ASTR)     // bf16 elems per array per stage

__device__ __forceinline__ void ldmat_x4(uint32_t& d0, uint32_t& d1, uint32_t& d2, uint32_t& d3,
                                         const __nv_bfloat16* p)
{
    uint32_t addr = (uint32_t)__cvta_generic_to_shared(p);
    asm volatile("ldmatrix.sync.aligned.m8n8.x4.shared.b16 {%0,%1,%2,%3}, [%4];"
                 : "=r"(d0), "=r"(d1), "=r"(d2), "=r"(d3) : "r"(addr));
}

__device__ __forceinline__ void mma_bf16(float* c, const uint32_t* a, uint32_t b0, uint32_t b1)
{
    asm volatile("mma.sync.aligned.m16n8k16.row.col.f32.bf16.bf16.f32 "
                 "{%0,%1,%2,%3}, {%4,%5,%6,%7}, {%8,%9}, {%0,%1,%2,%3};"
                 : "+f"(c[0]), "+f"(c[1]), "+f"(c[2]), "+f"(c[3])
                 : "r"(a[0]), "r"(a[1]), "r"(a[2]), "r"(a[3]), "r"(b0), "r"(b1));
}

__global__ __launch_bounds__(256)
void gemm_bf16x3(const __nv_bfloat16* __restrict__ Ah, const __nv_bfloat16* __restrict__ Al,
                 const __nv_bfloat16* __restrict__ Bh, const __nv_bfloat16* __restrict__ Bl,
                 float* __restrict__ C, int M, int N, int K)
{
    extern __shared__ __nv_bfloat16 sm[];
    const int tid = threadIdx.x;
    const int lane = tid & 31;
    const int wid = tid >> 5;
    const int bm = blockIdx.y * GBM;
    const int bn = blockIdx.x * GBN;
    const int wm = (wid >> 2) * 64;
    const int wn = (wid & 3) * 32;

    float acc[4][4][4];
#pragma unroll
    for (int a = 0; a < 4; a++)
#pragma unroll
        for (int b = 0; b < 4; b++)
#pragma unroll
            for (int c = 0; c < 4; c++) acc[a][b][c] = 0.f;

    const __nv_bfloat16* srcs[4] = { Ah, Al, Bh, Bl };

    // loader mapping: 2 chunks of 16B per array per thread
    const int c0 = tid * 2, c1 = tid * 2 + 1;
    const int r0 = c0 >> 2, kq0 = (c0 & 3) * 8;
    const int r1 = c1 >> 2, kq1 = (c1 & 3) * 8;

    const int nk = K / GBK;

    // ldmatrix lane addressing (shared by A and B)
    const int lrow = (lane & 7) + ((lane >> 3) & 1) * 8;
    const int lkof = (lane >> 4) * 8;

#define GLOAD(stage, k0)                                                              \
    do {                                                                              \
        _Pragma("unroll")                                                             \
        for (int arr = 0; arr < 4; arr++) {                                           \
            const __nv_bfloat16* s = srcs[arr];                                       \
            int rb = (arr < 2) ? bm : bn;                                             \
            __nv_bfloat16* dst = sm + ((stage) * 4 + arr) * GTILE;                    \
            {                                                                         \
                const __nv_bfloat16* g = s + (size_t)(rb + r0) * K + (k0) + kq0;      \
                uint32_t sa = (uint32_t)__cvta_generic_to_shared(dst + r0 * ASTR + kq0); \
                asm volatile("cp.async.cg.shared.global [%0], [%1], 16;" :: "r"(sa), "l"(g)); \
            }                                                                         \
            {                                                                         \
                const __nv_bfloat16* g = s + (size_t)(rb + r1) * K + (k0) + kq1;      \
                uint32_t sa = (uint32_t)__cvta_generic_to_shared(dst + r1 * ASTR + kq1); \
                asm volatile("cp.async.cg.shared.global [%0], [%1], 16;" :: "r"(sa), "l"(g)); \
            }                                                                         \
        }                                                                             \
        asm volatile("cp.async.commit_group;");                                       \
    } while (0)

    GLOAD(0, 0);

    for (int kt = 0; kt < nk; kt++) {
        if (kt + 1 < nk) {
            GLOAD((kt + 1) & 1, (kt + 1) * GBK);
            asm volatile("cp.async.wait_group 1;");
        } else {
            asm volatile("cp.async.wait_group 0;");
        }
        __syncthreads();

        const __nv_bfloat16* sAh = sm + ((kt & 1) * 4 + 0) * GTILE;
        const __nv_bfloat16* sAl = sm + ((kt & 1) * 4 + 1) * GTILE;
        const __nv_bfloat16* sBh = sm + ((kt & 1) * 4 + 2) * GTILE;
        const __nv_bfloat16* sBl = sm + ((kt & 1) * 4 + 3) * GTILE;

#pragma unroll
        for (int ks = 0; ks < 2; ks++) {
            uint32_t ah[4][4], al[4][4], bh[4][2], bl[4][2];
#pragma unroll
            for (int mf = 0; mf < 4; mf++) {
                const int off = (wm + mf * 16 + lrow) * ASTR + ks * 16 + lkof;
                ldmat_x4(ah[mf][0], ah[mf][1], ah[mf][2], ah[mf][3], sAh + off);
                ldmat_x4(al[mf][0], al[mf][1], al[mf][2], al[mf][3], sAl + off);
            }
#pragma unroll
            for (int nh = 0; nh < 2; nh++) {
                const int off = (wn + nh * 16 + lrow) * ASTR + ks * 16 + lkof;
                uint32_t d0, d1, d2, d3;
                ldmat_x4(d0, d1, d2, d3, sBh + off);
                bh[nh * 2][0] = d0;     bh[nh * 2][1] = d2;
                bh[nh * 2 + 1][0] = d1; bh[nh * 2 + 1][1] = d3;
                ldmat_x4(d0, d1, d2, d3, sBl + off);
                bl[nh * 2][0] = d0;     bl[nh * 2][1] = d2;
                bl[nh * 2 + 1][0] = d1; bl[nh * 2 + 1][1] = d3;
            }
#pragma unroll
            for (int mf = 0; mf < 4; mf++)
#pragma unroll
                for (int nf = 0; nf < 4; nf++) {
                    mma_bf16(acc[mf][nf], ah[mf], bh[nf][0], bh[nf][1]);
                    mma_bf16(acc[mf][nf], ah[mf], bl[nf][0], bl[nf][1]);
                    mma_bf16(acc[mf][nf], al[mf], bh[nf][0], bh[nf][1]);
                }
        }
        __syncthreads();
    }

    // epilogue
#pragma unroll
    for (int mf = 0; mf < 4; mf++)
#pragma unroll
        for (int nf = 0; nf < 4; nf++) {
            int row = bm + wm + mf * 16 + (lane >> 2);
            int col = bn + wn + nf * 8 + (lane & 3) * 2;
            *(float2*)&C[(size_t)row * N + col]       = make_float2(acc[mf][nf][0], acc[mf][nf][1]);
            *(float2*)&C[(size_t)(row + 8) * N + col] = make_float2(acc[mf][nf][2], acc[mf][nf][3]);
        }
}

// ---------------------------------------------------------------------------
// Softcap 50*tanh(s/50) via Taylor (|s/50| << 1 typically)
// ---------------------------------------------------------------------------
__device__ __forceinline__ float softcap50(float s)
{
    float x = s * 0.02f;
    float x2 = x * x;
    if (fabsf(x) < 0.39f) {
        float t = x * (1.0f + x2 * (-0.333333343f + x2 * (0.133333340f + x2 * (-0.0539682545f))));
        return 50.0f * t;
    }
    return 50.0f * tanhf(x);
}

#define NEG_BIG (-1.0e30f)

// ---------------------------------------------------------------------------
// Flash attention, fp32, causal, online softmax (unchanged from R1-pass).
// ---------------------------------------------------------------------------
__global__ __launch_bounds__(256)
void attn_kernel(const float* __restrict__ Q, const float* __restrict__ K,
                 const float* __restrict__ V, float* __restrict__ O)
{
    extern __shared__ float smem[];
    float* sQT = smem;
    float* sKV = smem + 128 * 64;
    float* sP  = smem + 2 * 128 * 64;

    const int qt = blockIdx.x;
    const int h  = blockIdx.y;
    const int b  = blockIdx.z;
    const int kvh = h >> 1;
    const int tid = threadIdx.x;
    const int tx = tid & 15;
    const int ty = tid >> 4;

    const int q0 = qt * 64;
    const size_t qhead = (size_t)b * SEQ * QDIM + (size_t)h * HD;
    const size_t khead = (size_t)b * SEQ * KVDIM + (size_t)kvh * HD;

    const float scale = 0.08838834764831845f;

#pragma unroll
    for (int t = 0; t < 8; t++) {
        int idx = tid + t * 256;
        int row = idx >> 5;
        int kq = (idx & 31) * 4;
        float4 v = *(const float4*)&Q[qhead + (size_t)(q0 + row) * QDIM + kq];
        sQT[(kq + 0) * 64 + row] = v.x * scale;
        sQT[(kq + 1) * 64 + row] = v.y * scale;
        sQT[(kq + 2) * 64 + row] = v.z * scale;
        sQT[(kq + 3) * 64 + row] = v.w * scale;
    }

    float m_i[4], l_i[4], acc[4][8];
#pragma unroll
    for (int i = 0; i < 4; i++) {
        m_i[i] = NEG_BIG; l_i[i] = 0.f;
#pragma unroll
        for (int j = 0; j < 8; j++) acc[i][j] = 0.f;
    }

    for (int kt = 0; kt <= qt; kt++) {
        const int k0 = kt * 64;
        __syncthreads();

#pragma unroll
        for (int t = 0; t < 8; t++) {
            int idx = tid + t * 256;
            int row = idx >> 5;
            int kq = (idx & 31) * 4;
            float4 v = *(const float4*)&K[khead + (size_t)(k0 + row) * KVDIM + kq];
            sKV[(kq + 0) * 64 + row] = v.x;
            sKV[(kq + 1) * 64 + row] = v.y;
            sKV[(kq + 2) * 64 + row] = v.z;
            sKV[(kq + 3) * 64 + row] = v.w;
        }
        __syncthreads();

        float S[4][4];
#pragma unroll
        for (int i = 0; i < 4; i++)
#pragma unroll
            for (int j = 0; j < 4; j++) S[i][j] = 0.f;

#pragma unroll 4
        for (int k = 0; k < 128; k++) {
            float a[4], bb[4];
#pragma unroll
            for (int i = 0; i < 4; i++) a[i]  = sQT[k * 64 + ty * 4 + i];
#pragma unroll
            for (int j = 0; j < 4; j++) bb[j] = sKV[k * 64 + tx * 4 + j];
#pragma unroll
            for (int i = 0; i < 4; i++)
#pragma unroll
                for (int j = 0; j < 4; j++)
                    S[i][j] += a[i] * bb[j];
        }

        const bool diag = (kt == qt);
#pragma unroll
        for (int i = 0; i < 4; i++) {
            const int qrow = q0 + ty * 4 + i;
#pragma unroll
            for (int j = 0; j < 4; j++) {
                float s = softcap50(S[i][j]);
                if (diag && (k0 + tx * 4 + j) > qrow) s = NEG_BIG;
                S[i][j] = s;
            }
            float mx = fmaxf(fmaxf(S[i][0], S[i][1]), fmaxf(S[i][2], S[i][3]));
#pragma unroll
            for (int off = 1; off < 16; off <<= 1)
                mx = fmaxf(mx, __shfl_xor_sync(0xffffffffu, mx, off));

            float m_new = fmaxf(m_i[i], mx);
            float corr = (m_i[i] < -1e29f) ? 0.f : __expf(m_i[i] - m_new);
            float rs = 0.f;
#pragma unroll
            for (int j = 0; j < 4; j++) {
                float p = (S[i][j] < -1e29f) ? 0.f : __expf(S[i][j] - m_new);
                S[i][j] = p;
                rs += p;
            }
#pragma unroll
            for (int off = 1; off < 16; off <<= 1)
                rs += __shfl_xor_sync(0xffffffffu, rs, off);

            l_i[i] = l_i[i] * corr + rs;
            m_i[i] = m_new;
#pragma unroll
            for (int j = 0; j < 8; j++) acc[i][j] *= corr;
        }

#pragma unroll
        for (int i = 0; i < 4; i++)
#pragma unroll
            for (int j = 0; j < 4; j++)
                sP[(ty * 4 + i) * 64 + tx * 4 + j] = S[i][j];
        __syncthreads();

#pragma unroll
        for (int t = 0; t < 8; t++) {
            int idx = tid + t * 256;
            int row = idx >> 5;
            int kq = (idx & 31) * 4;
            float4 v = *(const float4*)&V[khead + (size_t)(k0 + row) * KVDIM + kq];
            *(float4*)&sKV[row * 128 + kq] = v;
        }
        __syncthreads();

#pragma unroll 2
        for (int jj = 0; jj < 64; jj++) {
            float p[4], v[8];
#pragma unroll
            for (int i = 0; i < 4; i++) p[i] = sP[(ty * 4 + i) * 64 + jj];
#pragma unroll
            for (int j = 0; j < 8; j++) v[j] = sKV[jj * 128 + tx * 8 + j];
#pragma unroll
            for (int i = 0; i < 4; i++)
#pragma unroll
                for (int j = 0; j < 8; j++)
                    acc[i][j] += p[i] * v[j];
        }
    }

#pragma unroll
    for (int i = 0; i < 4; i++) {
        float inv = 1.0f / l_i[i];
        int row = q0 + ty * 4 + i;
        size_t obase = ((size_t)b * SEQ + row) * QDIM + (size_t)h * HD + tx * 8;
#pragma unroll
        for (int j = 0; j < 8; j++) acc[i][j] *= inv;
        *(float4*)&O[obase]     = make_float4(acc[i][0], acc[i][1], acc[i][2], acc[i][3]);
        *(float4*)&O[obase + 4] = make_float4(acc[i][4], acc[i][5], acc[i][6], acc[i][7]);
    }
}

// ---------------------------------------------------------------------------
extern "C" void kernel_launch(void* const* d_in, const int* in_sizes, int n_in,
                              void* d_out, int out_size)
{
    const float* x  = (const float*)d_in[0];
    const float* wq = (const float*)d_in[1];
    const float* wk = (const float*)d_in[2];
    const float* wv = (const float*)d_in[3];
    const float* wo = (const float*)d_in[4];
    float* out = (float*)d_out;

    float *Qp, *Kp, *Vp, *Op, *ropeT;
    cudaGetSymbolAddress((void**)&Qp, g_Q);
    cudaGetSymbolAddress((void**)&Kp, g_K);
    cudaGetSymbolAddress((void**)&Vp, g_V);
    cudaGetSymbolAddress((void**)&Op, g_O);
    cudaGetSymbolAddress((void**)&ropeT, g_rope);

    __nv_bfloat16 *xh, *xl, *wqh, *wql, *wkh, *wkl, *wvh, *wvl, *woh, *wol, *oh, *ol;
    cudaGetSymbolAddress((void**)&xh, g_xh);   cudaGetSymbolAddress((void**)&xl, g_xl);
    cudaGetSymbolAddress((void**)&wqh, g_wqh); cudaGetSymbolAddress((void**)&wql, g_wql);
    cudaGetSymbolAddress((void**)&wkh, g_wkh); cudaGetSymbolAddress((void**)&wkl, g_wkl);
    cudaGetSymbolAddress((void**)&wvh, g_wvh); cudaGetSymbolAddress((void**)&wvl, g_wvl);
    cudaGetSymbolAddress((void**)&woh, g_woh); cudaGetSymbolAddress((void**)&wol, g_wol);
    cudaGetSymbolAddress((void**)&oh, g_oh);   cudaGetSymbolAddress((void**)&ol, g_ol);

    static bool attrs_set = false;
    static const int GS = 2 * 4 * GTILE * 2;   // 81920 B
    static const int AS = (128 * 64 + 128 * 64 + 64 * 64) * 4;  // 80KB
    if (!attrs_set) {
        cudaFuncSetAttribute(gemm_bf16x3, cudaFuncAttributeMaxDynamicSharedMemorySize, GS);
        cudaFuncSetAttribute(attn_kernel, cudaFuncAttributeMaxDynamicSharedMemorySize, AS);
        attrs_set = true;
    }

    // 1. split inputs into bf16 hi/lo
    {
        int n;
        n = ROWS * DMODEL / 4;
        split4_kernel<<<(n + 255) / 256, 256>>>((const float4*)x, (__nv_bfloat162*)xh, (__nv_bfloat162*)xl, n);
        n = QDIM * DMODEL / 4;
        split4_kernel<<<(n + 255) / 256, 256>>>((const float4*)wq, (__nv_bfloat162*)wqh, (__nv_bfloat162*)wql, n);
        n = KVDIM * DMODEL / 4;
        split4_kernel<<<(n + 255) / 256, 256>>>((const float4*)wk, (__nv_bfloat162*)wkh, (__nv_bfloat162*)wkl, n);
        split4_kernel<<<(n + 255) / 256, 256>>>((const float4*)wv, (__nv_bfloat162*)wvh, (__nv_bfloat162*)wvl, n);
        n = DMODEL * QDIM / 4;
        split4_kernel<<<(n + 255) / 256, 256>>>((const float4*)wo, (__nv_bfloat162*)woh, (__nv_bfloat162*)wol, n);
    }

    // 2. rope table
    rope_table_kernel<<<(SEQ * 64 + 255) / 256, 256>>>(ropeT);

    // 3. QKV projections (tensor core, bf16x3)
    gemm_bf16x3<<<dim3(QDIM / GBN, ROWS / GBM), 256, GS>>>(xh, xl, wqh, wql, Qp, ROWS, QDIM, DMODEL);
    gemm_bf16x3<<<dim3(KVDIM / GBN, ROWS / GBM), 256, GS>>>(xh, xl, wkh, wkl, Kp, ROWS, KVDIM, DMODEL);
    gemm_bf16x3<<<dim3(KVDIM / GBN, ROWS / GBM), 256, GS>>>(xh, xl, wvh, wvl, Vp, ROWS, KVDIM, DMODEL);

    // 4. RoPE on Q and K
    {
        int totq = ROWS * NHEADS * 64;
        int totk = ROWS * NKV * 64;
        rope_apply_kernel<<<(totq + 255) / 256, 256>>>(Qp, ropeT, NHEADS, totq);
        rope_apply_kernel<<<(totk + 255) / 256, 256>>>(Kp, ropeT, NKV, totk);
    }

    // 5. Attention
    attn_kernel<<<dim3(SEQ / 64, NHEADS, BATCH), 256, AS>>>(Qp, Kp, Vp, Op);

    // 6. split attention output
    {
        int n = ROWS * QDIM / 4;
        split4_kernel<<<(n + 255) / 256, 256>>>((const float4*)Op, (__nv_bfloat162*)oh, (__nv_bfloat162*)ol, n);
    }

    // 7. output projection
    gemm_bf16x3<<<dim3(DMODEL / GBN, ROWS / GBM), 256, GS>>>(oh, ol, woh, wol, out, ROWS, DMODEL, DMODEL);
}

// round 3
// speedup vs baseline: 3.0288x; 1.7844x over previous
#include <cuda_runtime.h>
#include <cuda_bf16.h>
#include <math.h>
#include <stdint.h>

// Problem constants
#define BATCH 2
#define SEQ 2048
#define DMODEL 2048
#define NHEADS 16
#define NKV 8
#define HD 128
#define ROWS (BATCH*SEQ)          // 4096
#define QDIM (NHEADS*HD)          // 2048
#define KVDIM (NKV*HD)            // 1024

// fp32 scratch
__device__ float g_Q[(size_t)ROWS * QDIM];
__device__ float g_K[(size_t)ROWS * KVDIM];
__device__ float g_V[(size_t)ROWS * KVDIM];

// bf16 split scratch (hi / lo)
__device__ __nv_bfloat16 g_xh[(size_t)ROWS * DMODEL],  g_xl[(size_t)ROWS * DMODEL];
__device__ __nv_bfloat16 g_wqh[(size_t)QDIM * DMODEL], g_wql[(size_t)QDIM * DMODEL];
__device__ __nv_bfloat16 g_wkh[(size_t)KVDIM * DMODEL], g_wkl[(size_t)KVDIM * DMODEL];
__device__ __nv_bfloat16 g_wvh[(size_t)KVDIM * DMODEL], g_wvl[(size_t)KVDIM * DMODEL];
__device__ __nv_bfloat16 g_woh[(size_t)DMODEL * QDIM], g_wol[(size_t)DMODEL * QDIM];
__device__ __nv_bfloat16 g_oh[(size_t)ROWS * QDIM],   g_ol[(size_t)ROWS * QDIM];
// attention operand splits
__device__ __nv_bfloat16 g_qh[(size_t)ROWS * QDIM],  g_ql[(size_t)ROWS * QDIM];
__device__ __nv_bfloat16 g_kh[(size_t)ROWS * KVDIM], g_kl[(size_t)ROWS * KVDIM];
__device__ __nv_bfloat16 g_vh[(size_t)ROWS * KVDIM], g_vl[(size_t)ROWS * KVDIM];

// rope table: [pos][j] -> (cos, sin)
__device__ float g_rope[SEQ * 64 * 2];

// ---------------------------------------------------------------------------
__global__ void split4_kernel(const float4* __restrict__ src,
                              __nv_bfloat162* __restrict__ hi,
                              __nv_bfloat162* __restrict__ lo, int n4)
{
    int i = blockIdx.x * blockDim.x + threadIdx.x;
    if (i >= n4) return;
    float4 v = src[i];
    __nv_bfloat16 h0 = __float2bfloat16(v.x);
    __nv_bfloat16 h1 = __float2bfloat16(v.y);
    __nv_bfloat16 h2 = __float2bfloat16(v.z);
    __nv_bfloat16 h3 = __float2bfloat16(v.w);
    __nv_bfloat16 l0 = __float2bfloat16(v.x - __bfloat162float(h0));
    __nv_bfloat16 l1 = __float2bfloat16(v.y - __bfloat162float(h1));
    __nv_bfloat16 l2 = __float2bfloat16(v.z - __bfloat162float(h2));
    __nv_bfloat16 l3 = __float2bfloat16(v.w - __bfloat162float(h3));
    hi[i * 2]     = __nv_bfloat162(h0, h1);
    hi[i * 2 + 1] = __nv_bfloat162(h2, h3);
    lo[i * 2]     = __nv_bfloat162(l0, l1);
    lo[i * 2 + 1] = __nv_bfloat162(l2, l3);
}

// ---------------------------------------------------------------------------
__global__ void rope_table_kernel(float* __restrict__ tab)
{
    int i = blockIdx.x * blockDim.x + threadIdx.x;
    if (i >= SEQ * 64) return;
    int pos = i >> 6, j = i & 63;
    double inv = exp2(-(double)j * (13.287712379549449 / 64.0));
    double sd, cd;
    sincos((double)pos * inv, &sd, &cd);
    tab[i * 2]     = (float)cd;
    tab[i * 2 + 1] = (float)sd;
}

// scale folded in (1.0 for K, hd^-0.5 for Q)
__global__ void rope_apply_kernel(float* __restrict__ q, const float* __restrict__ tab,
                                  int n_heads, int total, float scale)
{
    int t = blockIdx.x * blockDim.x + threadIdx.x;
    if (t >= total) return;
    const int pairs_per_row = n_heads * 64;
    int row = t / pairs_per_row;
    int p = t - row * pairs_per_row;
    int head = p >> 6;
    int j = p & 63;
    int pos = row & (SEQ - 1);

    float cs = tab[(pos * 64 + j) * 2];
    float sn = tab[(pos * 64 + j) * 2 + 1];

    size_t base = (size_t)row * (pairs_per_row * 2) + (size_t)head * 128 + j;
    float a = q[base];
    float b = q[base + 64];
    q[base]      = (a * cs - b * sn) * scale;
    q[base + 64] = (b * cs + a * sn) * scale;
}

// ---------------------------------------------------------------------------
// MMA helpers
// ---------------------------------------------------------------------------
__device__ __forceinline__ void ldmat_x4(uint32_t& d0, uint32_t& d1, uint32_t& d2, uint32_t& d3,
                                         const __nv_bfloat16* p)
{
    uint32_t addr = (uint32_t)__cvta_generic_to_shared(p);
    asm volatile("ldmatrix.sync.aligned.m8n8.x4.shared.b16 {%0,%1,%2,%3}, [%4];"
                 : "=r"(d0), "=r"(d1), "=r"(d2), "=r"(d3) : "r"(addr));
}

__device__ __forceinline__ void ldmat_x4t(uint32_t& d0, uint32_t& d1, uint32_t& d2, uint32_t& d3,
                                          const __nv_bfloat16* p)
{
    uint32_t addr = (uint32_t)__cvta_generic_to_shared(p);
    asm volatile("ldmatrix.sync.aligned.m8n8.x4.trans.shared.b16 {%0,%1,%2,%3}, [%4];"
                 : "=r"(d0), "=r"(d1), "=r"(d2), "=r"(d3) : "r"(addr));
}

__device__ __forceinline__ void mma_bf16(float* c, const uint32_t* a, uint32_t b0, uint32_t b1)
{
    asm volatile("mma.sync.aligned.m16n8k16.row.col.f32.bf16.bf16.f32 "
                 "{%0,%1,%2,%3}, {%4,%5,%6,%7}, {%8,%9}, {%0,%1,%2,%3};"
                 : "+f"(c[0]), "+f"(c[1]), "+f"(c[2]), "+f"(c[3])
                 : "r"(a[0]), "r"(a[1]), "r"(a[2]), "r"(a[3]), "r"(b0), "r"(b1));
}

// ---------------------------------------------------------------------------
// bf16x3-split GEMM (unchanged from R2)
// ---------------------------------------------------------------------------
#define GBM 128
#define GBN 128
#define GBK 32
#define ASTR 40
#define GTILE (128 * ASTR)

__global__ __launch_bounds__(256)
void gemm_bf16x3(const __nv_bfloat16* __restrict__ Ah, const __nv_bfloat16* __restrict__ Al,
                 const __nv_bfloat16* __restrict__ Bh, const __nv_bfloat16* __restrict__ Bl,
                 float* __restrict__ C, int M, int N, int K)
{
    extern __shared__ __nv_bfloat16 sm[];
    const int tid = threadIdx.x;
    const int lane = tid & 31;
    const int wid = tid >> 5;
    const int bm = blockIdx.y * GBM;
    const int bn = blockIdx.x * GBN;
    const int wm = (wid >> 2) * 64;
    const int wn = (wid & 3) * 32;

    float acc[4][4][4];
#pragma unroll
    for (int a = 0; a < 4; a++)
#pragma unroll
        for (int b = 0; b < 4; b++)
#pragma unroll
            for (int c = 0; c < 4; c++) acc[a][b][c] = 0.f;

    const __nv_bfloat16* srcs[4] = { Ah, Al, Bh, Bl };

    const int c0 = tid * 2, c1 = tid * 2 + 1;
    const int r0 = c0 >> 2, kq0 = (c0 & 3) * 8;
    const int r1 = c1 >> 2, kq1 = (c1 & 3) * 8;

    const int nk = K / GBK;
    const int lrow = (lane & 7) + ((lane >> 3) & 1) * 8;
    const int lkof = (lane >> 4) * 8;

#define GLOAD(stage, k0)                                                              \
    do {                                                                              \
        _Pragma("unroll")                                                             \
        for (int arr = 0; arr < 4; arr++) {                                           \
            const __nv_bfloat16* s = srcs[arr];                                       \
            int rb = (arr < 2) ? bm : bn;                                             \
            __nv_bfloat16* dst = sm + ((stage) * 4 + arr) * GTILE;                    \
            {                                                                         \
                const __nv_bfloat16* g = s + (size_t)(rb + r0) * K + (k0) + kq0;      \
                uint32_t sa = (uint32_t)__cvta_generic_to_shared(dst + r0 * ASTR + kq0); \
                asm volatile("cp.async.cg.shared.global [%0], [%1], 16;" :: "r"(sa), "l"(g)); \
            }                                                                         \
            {                                                                         \
                const __nv_bfloat16* g = s + (size_t)(rb + r1) * K + (k0) + kq1;      \
                uint32_t sa = (uint32_t)__cvta_generic_to_shared(dst + r1 * ASTR + kq1); \
                asm volatile("cp.async.cg.shared.global [%0], [%1], 16;" :: "r"(sa), "l"(g)); \
            }                                                                         \
        }                                                                             \
        asm volatile("cp.async.commit_group;");                                       \
    } while (0)

    GLOAD(0, 0);

    for (int kt = 0; kt < nk; kt++) {
        if (kt + 1 < nk) {
            GLOAD((kt + 1) & 1, (kt + 1) * GBK);
            asm volatile("cp.async.wait_group 1;");
        } else {
            asm volatile("cp.async.wait_group 0;");
        }
        __syncthreads();

        const __nv_bfloat16* sAh = sm + ((kt & 1) * 4 + 0) * GTILE;
        const __nv_bfloat16* sAl = sm + ((kt & 1) * 4 + 1) * GTILE;
        const __nv_bfloat16* sBh = sm + ((kt & 1) * 4 + 2) * GTILE;
        const __nv_bfloat16* sBl = sm + ((kt & 1) * 4 + 3) * GTILE;

#pragma unroll
        for (int ks = 0; ks < 2; ks++) {
            uint32_t ah[4][4], al[4][4], bh[4][2], bl[4][2];
#pragma unroll
            for (int mf = 0; mf < 4; mf++) {
                const int off = (wm + mf * 16 + lrow) * ASTR + ks * 16 + lkof;
                ldmat_x4(ah[mf][0], ah[mf][1], ah[mf][2], ah[mf][3], sAh + off);
                ldmat_x4(al[mf][0], al[mf][1], al[mf][2], al[mf][3], sAl + off);
            }
#pragma unroll
            for (int nh = 0; nh < 2; nh++) {
                const int off = (wn + nh * 16 + lrow) * ASTR + ks * 16 + lkof;
                uint32_t d0, d1, d2, d3;
                ldmat_x4(d0, d1, d2, d3, sBh + off);
                bh[nh * 2][0] = d0;     bh[nh * 2][1] = d2;
                bh[nh * 2 + 1][0] = d1; bh[nh * 2 + 1][1] = d3;
                ldmat_x4(d0, d1, d2, d3, sBl + off);
                bl[nh * 2][0] = d0;     bl[nh * 2][1] = d2;
                bl[nh * 2 + 1][0] = d1; bl[nh * 2 + 1][1] = d3;
            }
#pragma unroll
            for (int mf = 0; mf < 4; mf++)
#pragma unroll
                for (int nf = 0; nf < 4; nf++) {
                    mma_bf16(acc[mf][nf], ah[mf], bh[nf][0], bh[nf][1]);
                    mma_bf16(acc[mf][nf], ah[mf], bl[nf][0], bl[nf][1]);
                    mma_bf16(acc[mf][nf], al[mf], bh[nf][0], bh[nf][1]);
                }
        }
        __syncthreads();
    }

#pragma unroll
    for (int mf = 0; mf < 4; mf++)
#pragma unroll
        for (int nf = 0; nf < 4; nf++) {
            int row = bm + wm + mf * 16 + (lane >> 2);
            int col = bn + wn + nf * 8 + (lane & 3) * 2;
            *(float2*)&C[(size_t)row * N + col]       = make_float2(acc[mf][nf][0], acc[mf][nf][1]);
            *(float2*)&C[(size_t)(row + 8) * N + col] = make_float2(acc[mf][nf][2], acc[mf][nf][3]);
        }
}

// ---------------------------------------------------------------------------
// helpers for attention
// ---------------------------------------------------------------------------
__device__ __forceinline__ float softcap50(float s)
{
    float x = s * 0.02f;
    float x2 = x * x;
    if (fabsf(x) < 0.39f) {
        float t = x * (1.0f + x2 * (-0.333333343f + x2 * (0.133333340f + x2 * (-0.0539682545f))));
        return 50.0f * t;
    }
    return 50.0f * tanhf(x);
}

// FMA-only exp (x <= 0; clamped), accuracy ~1e-7 rel
__device__ __forceinline__ float fexp(float x)
{
    x = fmaxf(x, -80.0f);
    float y = x * 1.44269504f;
    float r = rintf(y);
    float f = y - r;
    float p = 1.0f + f * (0.693147180f + f * (0.240226507f + f * (0.0555041087f +
              f * (0.00961812911f + f * 0.00133335581f))));
    return p * __int_as_float(((int)r + 127) << 23);
}

__device__ __forceinline__ uint32_t pack2bf(float a, float b)
{
    __nv_bfloat162 t = __floats2bfloat162_rn(a, b);
    return reinterpret_cast<uint32_t&>(t);
}

// ---------------------------------------------------------------------------
// Tensor-core flash attention. BM=64 q-rows per block, 4 warps x 16 rows.
// bf16 hi/lo (3-product) for QK^T and PV. Writes bf16 hi/lo output directly.
// ---------------------------------------------------------------------------
#define AT_STR 136     // 128 + 8 pad (272B rows, conflict-free ldmatrix)
#define AT_TILE (64 * AT_STR)

__global__ __launch_bounds__(128)
void attn_mma(const __nv_bfloat16* __restrict__ Qh, const __nv_bfloat16* __restrict__ Ql,
              const __nv_bfloat16* __restrict__ Kh, const __nv_bfloat16* __restrict__ Kl,
              const __nv_bfloat16* __restrict__ Vh, const __nv_bfloat16* __restrict__ Vl,
              __nv_bfloat16* __restrict__ Oh, __nv_bfloat16* __restrict__ Ol)
{
    extern __shared__ __nv_bfloat16 smb[];
    __nv_bfloat16* sQh = smb;
    __nv_bfloat16* sQl = smb + AT_TILE;
    __nv_bfloat16* sKh = smb + 2 * AT_TILE;
    __nv_bfloat16* sKl = smb + 3 * AT_TILE;
    __nv_bfloat16* sVh = smb + 4 * AT_TILE;
    __nv_bfloat16* sVl = smb + 5 * AT_TILE;

    const int qt = blockIdx.x;
    const int h  = blockIdx.y;
    const int b  = blockIdx.z;
    const int kvh = h >> 1;
    const int tid = threadIdx.x;
    const int lane = tid & 31;
    const int warp = tid >> 5;
    const int wm = warp * 16;

    const int q0 = qt * 64;
    const int lrow = (lane & 7) + ((lane >> 3) & 1) * 8;
    const int lkof = (lane >> 4) * 8;

    // ---- load Q tile (hi/lo) into smem via cp.async
    {
#pragma unroll
        for (int t = 0; t < 8; t++) {
            int c = tid + t * 128;         // 0..1023
            int row = c >> 4;
            int col = (c & 15) * 8;
            size_t g = ((size_t)(b * SEQ + q0 + row)) * QDIM + h * HD + col;
            uint32_t sa = (uint32_t)__cvta_generic_to_shared(sQh + row * AT_STR + col);
            asm volatile("cp.async.cg.shared.global [%0], [%1], 16;" :: "r"(sa), "l"(Qh + g));
            uint32_t sb = (uint32_t)__cvta_generic_to_shared(sQl + row * AT_STR + col);
            asm volatile("cp.async.cg.shared.global [%0], [%1], 16;" :: "r"(sb), "l"(Ql + g));
        }
        asm volatile("cp.async.commit_group;");
        asm volatile("cp.async.wait_group 0;");
    }

    float acc[16][4];
#pragma unroll
    for (int t = 0; t < 16; t++)
#pragma unroll
        for (int j = 0; j < 4; j++) acc[t][j] = 0.f;
    float m0 = -1e30f, m1 = -1e30f, l0 = 0.f, l1 = 0.f;

    for (int kt = 0; kt <= qt; kt++) {
        const int k0 = kt * 64;
        __syncthreads();   // prior-iter smem readers done; Q visible (iter 0)

        // K tile (hi/lo) — group A
#pragma unroll
        for (int t = 0; t < 8; t++) {
            int c = tid + t * 128;
            int row = c >> 4;
            int col = (c & 15) * 8;
            size_t g = ((size_t)(b * SEQ + k0 + row)) * KVDIM + kvh * HD + col;
            uint32_t sa = (uint32_t)__cvta_generic_to_shared(sKh + row * AT_STR + col);
            asm volatile("cp.async.cg.shared.global [%0], [%1], 16;" :: "r"(sa), "l"(Kh + g));
            uint32_t sb = (uint32_t)__cvta_generic_to_shared(sKl + row * AT_STR + col);
            asm volatile("cp.async.cg.shared.global [%0], [%1], 16;" :: "r"(sb), "l"(Kl + g));
        }
        asm volatile("cp.async.commit_group;");
        // V tile (hi/lo) — group B
#pragma unroll
        for (int t = 0; t < 8; t++) {
            int c = tid + t * 128;
            int row = c >> 4;
            int col = (c & 15) * 8;
            size_t g = ((size_t)(b * SEQ + k0 + row)) * KVDIM + kvh * HD + col;
            uint32_t sa = (uint32_t)__cvta_generic_to_shared(sVh + row * AT_STR + col);
            asm volatile("cp.async.cg.shared.global [%0], [%1], 16;" :: "r"(sa), "l"(Vh + g));
            uint32_t sb = (uint32_t)__cvta_generic_to_shared(sVl + row * AT_STR + col);
            asm volatile("cp.async.cg.shared.global [%0], [%1], 16;" :: "r"(sb), "l"(Vl + g));
        }
        asm volatile("cp.async.commit_group;");

        asm volatile("cp.async.wait_group 1;");   // K ready (V in flight)
        __syncthreads();

        // ---- S = Q K^T (bf16x3)
        float S[8][4];
#pragma unroll
        for (int t = 0; t < 8; t++)
#pragma unroll
            for (int j = 0; j < 4; j++) S[t][j] = 0.f;

#pragma unroll
        for (int ks = 0; ks < 8; ks++) {
            uint32_t ah[4], al[4];
            ldmat_x4(ah[0], ah[1], ah[2], ah[3], sQh + (wm + lrow) * AT_STR + ks * 16 + lkof);
            ldmat_x4(al[0], al[1], al[2], al[3], sQl + (wm + lrow) * AT_STR + ks * 16 + lkof);
#pragma unroll
            for (int nh = 0; nh < 4; nh++) {
                uint32_t d0, d1, d2, d3, e0, e1, e2, e3;
                ldmat_x4(d0, d1, d2, d3, sKh + (nh * 16 + lrow) * AT_STR + ks * 16 + lkof);
                ldmat_x4(e0, e1, e2, e3, sKl + (nh * 16 + lrow) * AT_STR + ks * 16 + lkof);
                mma_bf16(S[2 * nh], ah, d0, d2);
                mma_bf16(S[2 * nh], ah, e0, e2);
                mma_bf16(S[2 * nh], al, d0, d2);
                mma_bf16(S[2 * nh + 1], ah, d1, d3);
                mma_bf16(S[2 * nh + 1], ah, e1, e3);
                mma_bf16(S[2 * nh + 1], al, d1, d3);
            }
        }

        // ---- softcap + mask + online softmax
#pragma unroll
        for (int t = 0; t < 8; t++)
#pragma unroll
            for (int j = 0; j < 4; j++) S[t][j] = softcap50(S[t][j]);

        if (kt == qt) {
            const int r0g = q0 + wm + (lane >> 2);
#pragma unroll
            for (int t = 0; t < 8; t++) {
                int cb = k0 + t * 8 + 2 * (lane & 3);
                if (cb > r0g)         S[t][0] = -30000.f;
                if (cb + 1 > r0g)     S[t][1] = -30000.f;
                if (cb > r0g + 8)     S[t][2] = -30000.f;
                if (cb + 1 > r0g + 8) S[t][3] = -30000.f;
            }
        }

        float mx0 = -1e30f, mx1 = -1e30f;
#pragma unroll
        for (int t = 0; t < 8; t++) {
            mx0 = fmaxf(mx0, fmaxf(S[t][0], S[t][1]));
            mx1 = fmaxf(mx1, fmaxf(S[t][2], S[t][3]));
        }
        mx0 = fmaxf(mx0, __shfl_xor_sync(0xffffffffu, mx0, 1));
        mx0 = fmaxf(mx0, __shfl_xor_sync(0xffffffffu, mx0, 2));
        mx1 = fmaxf(mx1, __shfl_xor_sync(0xffffffffu, mx1, 1));
        mx1 = fmaxf(mx1, __shfl_xor_sync(0xffffffffu, mx1, 2));

        float m0n = fmaxf(m0, mx0);
        float m1n = fmaxf(m1, mx1);
        float corr0 = fexp(m0 - m0n);
        float corr1 = fexp(m1 - m1n);

        float rs0 = 0.f, rs1 = 0.f;
#pragma unroll
        for (int t = 0; t < 8; t++) {
            S[t][0] = fexp(S[t][0] - m0n);
            S[t][1] = fexp(S[t][1] - m0n);
            S[t][2] = fexp(S[t][2] - m1n);
            S[t][3] = fexp(S[t][3] - m1n);
            rs0 += S[t][0] + S[t][1];
            rs1 += S[t][2] + S[t][3];
        }
        rs0 += __shfl_xor_sync(0xffffffffu, rs0, 1);
        rs0 += __shfl_xor_sync(0xffffffffu, rs0, 2);
        rs1 += __shfl_xor_sync(0xffffffffu, rs1, 1);
        rs1 += __shfl_xor_sync(0xffffffffu, rs1, 2);

        l0 = l0 * corr0 + rs0;  m0 = m0n;
        l1 = l1 * corr1 + rs1;  m1 = m1n;

#pragma unroll
        for (int t = 0; t < 16; t++) {
            acc[t][0] *= corr0; acc[t][1] *= corr0;
            acc[t][2] *= corr1; acc[t][3] *= corr1;
        }

        asm volatile("cp.async.wait_group 0;");   // V ready
        __syncthreads();

        // ---- O += P V (bf16x3); P fragments built in registers from S
#pragma unroll
        for (int pk = 0; pk < 4; pk++) {
            uint32_t ph[4], pl[4];
            float v, hv;
            float hA[8], lA[8];
#pragma unroll
            for (int e = 0; e < 4; e++) {
                v = S[2 * pk][e];     hv = __bfloat162float(__float2bfloat16(v));
                hA[e] = hv; lA[e] = v - hv;
                v = S[2 * pk + 1][e]; hv = __bfloat162float(__float2bfloat16(v));
                hA[4 + e] = hv; lA[4 + e] = v - hv;
            }
            ph[0] = pack2bf(hA[0], hA[1]); ph[1] = pack2bf(hA[2], hA[3]);
            ph[2] = pack2bf(hA[4], hA[5]); ph[3] = pack2bf(hA[6], hA[7]);
            pl[0] = pack2bf(lA[0], lA[1]); pl[1] = pack2bf(lA[2], lA[3]);
            pl[2] = pack2bf(lA[4], lA[5]); pl[3] = pack2bf(lA[6], lA[7]);

#pragma unroll
            for (int nh = 0; nh < 8; nh++) {
                uint32_t d0, d1, d2, d3, e0, e1, e2, e3;
                ldmat_x4t(d0, d1, d2, d3, sVh + (pk * 16 + lrow) * AT_STR + nh * 16 + lkof);
                ldmat_x4t(e0, e1, e2, e3, sVl + (pk * 16 + lrow) * AT_STR + nh * 16 + lkof);
                mma_bf16(acc[2 * nh], ph, d0, d1);
                mma_bf16(acc[2 * nh], ph, e0, e1);
                mma_bf16(acc[2 * nh], pl, d0, d1);
                mma_bf16(acc[2 * nh + 1], ph, d2, d3);
                mma_bf16(acc[2 * nh + 1], ph, e2, e3);
                mma_bf16(acc[2 * nh + 1], pl, d2, d3);
            }
        }
    }

    // ---- epilogue: normalize, split to bf16 hi/lo, store
    float inv0 = 1.0f / l0;
    float inv1 = 1.0f / l1;
    size_t row0 = (size_t)(b * SEQ + q0 + wm + (lane >> 2));
    size_t row1 = row0 + 8;
    int colb = h * HD + 2 * (lane & 3);
#pragma unroll
    for (int t = 0; t < 16; t++) {
        float v0 = acc[t][0] * inv0, v1 = acc[t][1] * inv0;
        float v2 = acc[t][2] * inv1, v3 = acc[t][3] * inv1;
        float h0 = __bfloat162float(__float2bfloat16(v0));
        float h1 = __bfloat162float(__float2bfloat16(v1));
        float h2 = __bfloat162float(__float2bfloat16(v2));
        float h3 = __bfloat162float(__float2bfloat16(v3));
        size_t o0 = row0 * QDIM + colb + t * 8;
        size_t o1 = row1 * QDIM + colb + t * 8;
        *(uint32_t*)&Oh[o0] = pack2bf(h0, h1);
        *(uint32_t*)&Ol[o0] = pack2bf(v0 - h0, v1 - h1);
        *(uint32_t*)&Oh[o1] = pack2bf(h2, h3);
        *(uint32_t*)&Ol[o1] = pack2bf(v2 - h2, v3 - h3);
    }
}

// ---------------------------------------------------------------------------
extern "C" void kernel_launch(void* const* d_in, const int* in_sizes, int n_in,
                              void* d_out, int out_size)
{
    const float* x  = (const float*)d_in[0];
    const float* wq = (const float*)d_in[1];
    const float* wk = (const float*)d_in[2];
    const float* wv = (const float*)d_in[3];
    const float* wo = (const float*)d_in[4];
    float* out = (float*)d_out;

    float *Qp, *Kp, *Vp, *ropeT;
    cudaGetSymbolAddress((void**)&Qp, g_Q);
    cudaGetSymbolAddress((void**)&Kp, g_K);
    cudaGetSymbolAddress((void**)&Vp, g_V);
    cudaGetSymbolAddress((void**)&ropeT, g_rope);

    __nv_bfloat16 *xh, *xl, *wqh, *wql, *wkh, *wkl, *wvh, *wvl, *woh, *wol, *oh, *ol;
    __nv_bfloat16 *qh, *ql, *kh, *kl, *vh, *vl;
    cudaGetSymbolAddress((void**)&xh, g_xh);   cudaGetSymbolAddress((void**)&xl, g_xl);
    cudaGetSymbolAddress((void**)&wqh, g_wqh); cudaGetSymbolAddress((void**)&wql, g_wql);
    cudaGetSymbolAddress((void**)&wkh, g_wkh); cudaGetSymbolAddress((void**)&wkl, g_wkl);
    cudaGetSymbolAddress((void**)&wvh, g_wvh); cudaGetSymbolAddress((void**)&wvl, g_wvl);
    cudaGetSymbolAddress((void**)&woh, g_woh); cudaGetSymbolAddress((void**)&wol, g_wol);
    cudaGetSymbolAddress((void**)&oh, g_oh);   cudaGetSymbolAddress((void**)&ol, g_ol);
    cudaGetSymbolAddress((void**)&qh, g_qh);   cudaGetSymbolAddress((void**)&ql, g_ql);
    cudaGetSymbolAddress((void**)&kh, g_kh);   cudaGetSymbolAddress((void**)&kl, g_kl);
    cudaGetSymbolAddress((void**)&vh, g_vh);   cudaGetSymbolAddress((void**)&vl, g_vl);

    static bool attrs_set = false;
    static const int GS = 2 * 4 * GTILE * 2;        // 81920 B
    static const int AS = 6 * AT_TILE * 2;          // 104448 B
    if (!attrs_set) {
        cudaFuncSetAttribute(gemm_bf16x3, cudaFuncAttributeMaxDynamicSharedMemorySize, GS);
        cudaFuncSetAttribute(attn_mma, cudaFuncAttributeMaxDynamicSharedMemorySize, AS);
        attrs_set = true;
    }

    // 1. split inputs into bf16 hi/lo
    {
        int n;
        n = ROWS * DMODEL / 4;
        split4_kernel<<<(n + 255) / 256, 256>>>((const float4*)x, (__nv_bfloat162*)xh, (__nv_bfloat162*)xl, n);
        n = QDIM * DMODEL / 4;
        split4_kernel<<<(n + 255) / 256, 256>>>((const float4*)wq, (__nv_bfloat162*)wqh, (__nv_bfloat162*)wql, n);
        n = KVDIM * DMODEL / 4;
        split4_kernel<<<(n + 255) / 256, 256>>>((const float4*)wk, (__nv_bfloat162*)wkh, (__nv_bfloat162*)wkl, n);
        split4_kernel<<<(n + 255) / 256, 256>>>((const float4*)wv, (__nv_bfloat162*)wvh, (__nv_bfloat162*)wvl, n);
        n = DMODEL * QDIM / 4;
        split4_kernel<<<(n + 255) / 256, 256>>>((const float4*)wo, (__nv_bfloat162*)woh, (__nv_bfloat162*)wol, n);
    }

    // 2. rope table
    rope_table_kernel<<<(SEQ * 64 + 255) / 256, 256>>>(ropeT);

    // 3. QKV projections
    gemm_bf16x3<<<dim3(QDIM / GBN, ROWS / GBM), 256, GS>>>(xh, xl, wqh, wql, Qp, ROWS, QDIM, DMODEL);
    gemm_bf16x3<<<dim3(KVDIM / GBN, ROWS / GBM), 256, GS>>>(xh, xl, wkh, wkl, Kp, ROWS, KVDIM, DMODEL);
    gemm_bf16x3<<<dim3(KVDIM / GBN, ROWS / GBM), 256, GS>>>(xh, xl, wvh, wvl, Vp, ROWS, KVDIM, DMODEL);

    // 4. RoPE (Q gets attention scale folded in)
    {
        int totq = ROWS * NHEADS * 64;
        int totk = ROWS * NKV * 64;
        rope_apply_kernel<<<(totq + 255) / 256, 256>>>(Qp, ropeT, NHEADS, totq, 0.08838834764831845f);
        rope_apply_kernel<<<(totk + 255) / 256, 256>>>(Kp, ropeT, NKV, totk, 1.0f);
    }

    // 5. split Q/K/V for tensor-core attention
    {
        int n = ROWS * QDIM / 4;
        split4_kernel<<<(n + 255) / 256, 256>>>((const float4*)Qp, (__nv_bfloat162*)qh, (__nv_bfloat162*)ql, n);
        n = ROWS * KVDIM / 4;
        split4_kernel<<<(n + 255) / 256, 256>>>((const float4*)Kp, (__nv_bfloat162*)kh, (__nv_bfloat162*)kl, n);
        split4_kernel<<<(n + 255) / 256, 256>>>((const float4*)Vp, (__nv_bfloat162*)vh, (__nv_bfloat162*)vl, n);
    }

    // 6. attention (writes bf16 hi/lo output directly)
    attn_mma<<<dim3(SEQ / 64, NHEADS, BATCH), 128, AS>>>(qh, ql, kh, kl, vh, vl, oh, ol);

    // 7. output projection
    gemm_bf16x3<<<dim3(DMODEL / GBN, ROWS / GBM), 256, GS>>>(oh, ol, woh, wol, out, ROWS, DMODEL, DMODEL);
}

// round 6
// speedup vs baseline: 4.2042x; 1.3881x over previous
#include <cuda_runtime.h>
#include <cuda_fp16.h>
#include <math.h>
#include <stdint.h>

// Problem constants
#define BATCH 2
#define SEQ 2048
#define DMODEL 2048
#define NHEADS 16
#define NKV 8
#define HD 128
#define ROWS (BATCH*SEQ)          // 4096
#define QDIM (NHEADS*HD)          // 2048
#define KVDIM (NKV*HD)            // 1024

// fp32 scratch
__device__ float g_Q[(size_t)ROWS * QDIM];
__device__ float g_K[(size_t)ROWS * KVDIM];
__device__ float g_V[(size_t)ROWS * KVDIM];

// fp16 operands
__device__ __half g_xh[(size_t)ROWS * DMODEL],  g_xl[(size_t)ROWS * DMODEL];   // x hi/lo
__device__ __half g_wq16[(size_t)QDIM * DMODEL];                                // weights plain
__device__ __half g_wk16[(size_t)KVDIM * DMODEL];
__device__ __half g_wv16[(size_t)KVDIM * DMODEL];
__device__ __half g_wo16[(size_t)DMODEL * QDIM];
__device__ __half g_oh[(size_t)ROWS * QDIM], g_ol[(size_t)ROWS * QDIM];         // attn out hi/lo
__device__ __half g_qh[(size_t)ROWS * QDIM], g_ql[(size_t)ROWS * QDIM];         // Q hi/lo
__device__ __half g_k16[(size_t)ROWS * KVDIM];                                  // K plain
__device__ __half g_v16[(size_t)ROWS * KVDIM];                                  // V plain

// rope table: [pos][j] -> (cos, sin)
__device__ float g_rope[SEQ * 64 * 2];

// ---------------------------------------------------------------------------
// fp32 -> fp16 hi/lo split (x4)
__global__ void split4h_kernel(const float4* __restrict__ src,
                               __half2* __restrict__ hi, __half2* __restrict__ lo, int n4)
{
    int i = blockIdx.x * blockDim.x + threadIdx.x;
    if (i >= n4) return;
    float4 v = src[i];
    __half h0 = __float2half_rn(v.x), h1 = __float2half_rn(v.y);
    __half h2 = __float2half_rn(v.z), h3 = __float2half_rn(v.w);
    hi[i * 2]     = __half2(h0, h1);
    hi[i * 2 + 1] = __half2(h2, h3);
    lo[i * 2]     = __half2(__float2half_rn(v.x - __half2float(h0)), __float2half_rn(v.y - __half2float(h1)));
    lo[i * 2 + 1] = __half2(__float2half_rn(v.z - __half2float(h2)), __float2half_rn(v.w - __half2float(h3)));
}

// fp32 -> fp16 plain (x4)
__global__ void cvt4h_kernel(const float4* __restrict__ src, __half2* __restrict__ dst, int n4)
{
    int i = blockIdx.x * blockDim.x + threadIdx.x;
    if (i >= n4) return;
    float4 v = src[i];
    dst[i * 2]     = __floats2half2_rn(v.x, v.y);
    dst[i * 2 + 1] = __floats2half2_rn(v.z, v.w);
}

// ---------------------------------------------------------------------------
__global__ void rope_table_kernel(float* __restrict__ tab)
{
    int i = blockIdx.x * blockDim.x + threadIdx.x;
    if (i >= SEQ * 64) return;
    int pos = i >> 6, j = i & 63;
    double inv = exp2(-(double)j * (13.287712379549449 / 64.0));
    double sd, cd;
    sincos((double)pos * inv, &sd, &cd);
    tab[i * 2]     = (float)cd;
    tab[i * 2 + 1] = (float)sd;
}

// rope + fp16 hi/lo split (for Q; scale folded)
__global__ void rope_split_kernel(const float* __restrict__ q, const float* __restrict__ tab,
                                  __half* __restrict__ qhi, __half* __restrict__ qlo,
                                  int n_heads, int total, float scale)
{
    int t = blockIdx.x * blockDim.x + threadIdx.x;
    if (t >= total) return;
    const int pairs_per_row = n_heads * 64;
    int row = t / pairs_per_row;
    int p = t - row * pairs_per_row;
    int head = p >> 6;
    int j = p & 63;
    int pos = row & (SEQ - 1);

    float cs = tab[(pos * 64 + j) * 2];
    float sn = tab[(pos * 64 + j) * 2 + 1];

    size_t base = (size_t)row * (pairs_per_row * 2) + (size_t)head * 128 + j;
    float a = q[base];
    float b = q[base + 64];
    float v0 = (a * cs - b * sn) * scale;
    float v1 = (b * cs + a * sn) * scale;
    __half h0 = __float2half_rn(v0);
    __half h1 = __float2half_rn(v1);
    qhi[base]      = h0;
    qhi[base + 64] = h1;
    qlo[base]      = __float2half_rn(v0 - __half2float(h0));
    qlo[base + 64] = __float2half_rn(v1 - __half2float(h1));
}

// rope + plain fp16 convert (for K)
__global__ void rope_cvt_kernel(const float* __restrict__ q, const float* __restrict__ tab,
                                __half* __restrict__ out, int n_heads, int total)
{
    int t = blockIdx.x * blockDim.x + threadIdx.x;
    if (t >= total) return;
    const int pairs_per_row = n_heads * 64;
    int row = t / pairs_per_row;
    int p = t - row * pairs_per_row;
    int head = p >> 6;
    int j = p & 63;
    int pos = row & (SEQ - 1);

    float cs = tab[(pos * 64 + j) * 2];
    float sn = tab[(pos * 64 + j) * 2 + 1];

    size_t base = (size_t)row * (pairs_per_row * 2) + (size_t)head * 128 + j;
    float a = q[base];
    float b = q[base + 64];
    out[base]      = __float2half_rn(a * cs - b * sn);
    out[base + 64] = __float2half_rn(b * cs + a * sn);
}

// ---------------------------------------------------------------------------
// MMA helpers (fp16)
// ---------------------------------------------------------------------------
__device__ __forceinline__ void ldmat_x4(uint32_t& d0, uint32_t& d1, uint32_t& d2, uint32_t& d3,
                                         const __half* p)
{
    uint32_t addr = (uint32_t)__cvta_generic_to_shared(p);
    asm volatile("ldmatrix.sync.aligned.m8n8.x4.shared.b16 {%0,%1,%2,%3}, [%4];"
                 : "=r"(d0), "=r"(d1), "=r"(d2), "=r"(d3) : "r"(addr));
}

__device__ __forceinline__ void ldmat_x4t(uint32_t& d0, uint32_t& d1, uint32_t& d2, uint32_t& d3,
                                          const __half* p)
{
    uint32_t addr = (uint32_t)__cvta_generic_to_shared(p);
    asm volatile("ldmatrix.sync.aligned.m8n8.x4.trans.shared.b16 {%0,%1,%2,%3}, [%4];"
                 : "=r"(d0), "=r"(d1), "=r"(d2), "=r"(d3) : "r"(addr));
}

__device__ __forceinline__ void mma_f16(float* c, const uint32_t* a, uint32_t b0, uint32_t b1)
{
    asm volatile("mma.sync.aligned.m16n8k16.row.col.f32.f16.f16.f32 "
                 "{%0,%1,%2,%3}, {%4,%5,%6,%7}, {%8,%9}, {%0,%1,%2,%3};"
                 : "+f"(c[0]), "+f"(c[1]), "+f"(c[2]), "+f"(c[3])
                 : "r"(a[0]), "r"(a[1]), "r"(a[2]), "r"(a[3]), "r"(b0), "r"(b1));
}

// ---------------------------------------------------------------------------
// fp16x2 GEMM: C = (Ah+Al) @ B^T, A split (exact), B plain fp16.
// BM=BN=128, BK=32, 256 threads, warp tile 64x32. 2 MMAs per fragment pair.
// ---------------------------------------------------------------------------
#define GBM 128
#define GBN 128
#define GBK 32
#define ASTR 40
#define GTILE (128 * ASTR)     // halfs per array per stage

__global__ __launch_bounds__(256)
void gemm_f16x2(const __half* __restrict__ Ah, const __half* __restrict__ Al,
                const __half* __restrict__ B, float* __restrict__ C, int M, int N, int K)
{
    extern __shared__ __half smh[];
    const int tid = threadIdx.x;
    const int lane = tid & 31;
    const int wid = tid >> 5;
    const int bm = blockIdx.y * GBM;
    const int bn = blockIdx.x * GBN;
    const int wm = (wid >> 2) * 64;
    const int wn = (wid & 3) * 32;

    float acc[4][4][4];
#pragma unroll
    for (int a = 0; a < 4; a++)
#pragma unroll
        for (int b = 0; b < 4; b++)
#pragma unroll
            for (int c = 0; c < 4; c++) acc[a][b][c] = 0.f;

    const __half* srcs[3] = { Ah, Al, B };

    const int c0 = tid * 2, c1 = tid * 2 + 1;
    const int r0 = c0 >> 2, kq0 = (c0 & 3) * 8;
    const int r1 = c1 >> 2, kq1 = (c1 & 3) * 8;

    const int nk = K / GBK;
    const int lrow = (lane & 7) + ((lane >> 3) & 1) * 8;
    const int lkof = (lane >> 4) * 8;

#define GLOAD(stage, k0)                                                              \
    do {                                                                              \
        _Pragma("unroll")                                                             \
        for (int arr = 0; arr < 3; arr++) {                                           \
            const __half* s = srcs[arr];                                              \
            int rb = (arr < 2) ? bm : bn;                                             \
            __half* dst = smh + ((stage) * 3 + arr) * GTILE;                          \
            {                                                                         \
                const __half* g = s + (size_t)(rb + r0) * K + (k0) + kq0;             \
                uint32_t sa = (uint32_t)__cvta_generic_to_shared(dst + r0 * ASTR + kq0); \
                asm volatile("cp.async.cg.shared.global [%0], [%1], 16;" :: "r"(sa), "l"(g)); \
            }                                                                         \
            {                                                                         \
                const __half* g = s + (size_t)(rb + r1) * K + (k0) + kq1;             \
                uint32_t sa = (uint32_t)__cvta_generic_to_shared(dst + r1 * ASTR + kq1); \
                asm volatile("cp.async.cg.shared.global [%0], [%1], 16;" :: "r"(sa), "l"(g)); \
            }                                                                         \
        }                                                                             \
        asm volatile("cp.async.commit_group;");                                       \
    } while (0)

    GLOAD(0, 0);

    for (int kt = 0; kt < nk; kt++) {
        if (kt + 1 < nk) {
            GLOAD((kt + 1) & 1, (kt + 1) * GBK);
            asm volatile("cp.async.wait_group 1;");
        } else {
            asm volatile("cp.async.wait_group 0;");
        }
        __syncthreads();

        const __half* sAh = smh + ((kt & 1) * 3 + 0) * GTILE;
        const __half* sAl = smh + ((kt & 1) * 3 + 1) * GTILE;
        const __half* sB  = smh + ((kt & 1) * 3 + 2) * GTILE;

#pragma unroll
        for (int ks = 0; ks < 2; ks++) {
            uint32_t ah[4][4], al[4][4], bb[4][2];
#pragma unroll
            for (int mf = 0; mf < 4; mf++) {
                const int off = (wm + mf * 16 + lrow) * ASTR + ks * 16 + lkof;
                ldmat_x4(ah[mf][0], ah[mf][1], ah[mf][2], ah[mf][3], sAh + off);
                ldmat_x4(al[mf][0], al[mf][1], al[mf][2], al[mf][3], sAl + off);
            }
#pragma unroll
            for (int nh = 0; nh < 2; nh++) {
                const int off = (wn + nh * 16 + lrow) * ASTR + ks * 16 + lkof;
                uint32_t d0, d1, d2, d3;
                ldmat_x4(d0, d1, d2, d3, sB + off);
                bb[nh * 2][0] = d0;     bb[nh * 2][1] = d2;
                bb[nh * 2 + 1][0] = d1; bb[nh * 2 + 1][1] = d3;
            }
#pragma unroll
            for (int mf = 0; mf < 4; mf++)
#pragma unroll
                for (int nf = 0; nf < 4; nf++) {
                    mma_f16(acc[mf][nf], ah[mf], bb[nf][0], bb[nf][1]);
                    mma_f16(acc[mf][nf], al[mf], bb[nf][0], bb[nf][1]);
                }
        }
        __syncthreads();
    }

#pragma unroll
    for (int mf = 0; mf < 4; mf++)
#pragma unroll
        for (int nf = 0; nf < 4; nf++) {
            int row = bm + wm + mf * 16 + (lane >> 2);
            int col = bn + wn + nf * 8 + (lane & 3) * 2;
            *(float2*)&C[(size_t)row * N + col]       = make_float2(acc[mf][nf][0], acc[mf][nf][1]);
            *(float2*)&C[(size_t)(row + 8) * N + col] = make_float2(acc[mf][nf][2], acc[mf][nf][3]);
        }
}

// ---------------------------------------------------------------------------
// attention helpers
// ---------------------------------------------------------------------------
__device__ __forceinline__ float softcap50(float s)
{
    float x = s * 0.02f;
    float x2 = x * x;
    if (fabsf(x) < 0.39f) {
        float t = x * (1.0f + x2 * (-0.333333343f + x2 * (0.133333340f + x2 * (-0.0539682545f))));
        return 50.0f * t;
    }
    return 50.0f * tanhf(x);
}

__device__ __forceinline__ float fexp(float x)
{
    x = fmaxf(x, -80.0f);
    float y = x * 1.44269504f;
    float r = rintf(y);
    float f = y - r;
    float p = 1.0f + f * (0.693147180f + f * (0.240226507f + f * (0.0555041087f +
              f * (0.00961812911f + f * 0.00133335581f))));
    return p * __int_as_float(((int)r + 127) << 23);
}

__device__ __forceinline__ uint32_t pack2h(float a, float b)
{
    __half2 t = __floats2half2_rn(a, b);
    return reinterpret_cast<uint32_t&>(t);
}

// ---------------------------------------------------------------------------
// fp16 flash attention: Q split (hi/lo), K plain, P split, V plain.
// BM=64, 4 warps x 16 rows. smem: sQh|sQl|sK|sV (4 tiles, 68KB).
// ---------------------------------------------------------------------------
#define AT_STR 136
#define AT_TILE (64 * AT_STR)

__global__ __launch_bounds__(128)
void attn_f16(const __half* __restrict__ Qh, const __half* __restrict__ Ql,
              const __half* __restrict__ Kp, const __half* __restrict__ Vp,
              __half* __restrict__ Oh, __half* __restrict__ Ol)
{
    extern __shared__ __half smf[];
    __half* sQh = smf;
    __half* sQl = smf + AT_TILE;
    __half* sK  = smf + 2 * AT_TILE;
    __half* sV  = smf + 3 * AT_TILE;

    const int qt = blockIdx.x;
    const int h  = blockIdx.y;
    const int b  = blockIdx.z;
    const int kvh = h >> 1;
    const int tid = threadIdx.x;
    const int lane = tid & 31;
    const int warp = tid >> 5;
    const int wm = warp * 16;

    const int q0 = qt * 64;
    const int lrow = (lane & 7) + ((lane >> 3) & 1) * 8;
    const int lkof = (lane >> 4) * 8;

    // Q tile (hi/lo)
    {
#pragma unroll
        for (int t = 0; t < 8; t++) {
            int c = tid + t * 128;
            int row = c >> 4;
            int col = (c & 15) * 8;
            size_t g = ((size_t)(b * SEQ + q0 + row)) * QDIM + h * HD + col;
            uint32_t sa = (uint32_t)__cvta_generic_to_shared(sQh + row * AT_STR + col);
            asm volatile("cp.async.cg.shared.global [%0], [%1], 16;" :: "r"(sa), "l"(Qh + g));
            uint32_t sb = (uint32_t)__cvta_generic_to_shared(sQl + row * AT_STR + col);
            asm volatile("cp.async.cg.shared.global [%0], [%1], 16;" :: "r"(sb), "l"(Ql + g));
        }
        asm volatile("cp.async.commit_group;");
        asm volatile("cp.async.wait_group 0;");
    }

    float acc[16][4];
#pragma unroll
    for (int t = 0; t < 16; t++)
#pragma unroll
        for (int j = 0; j < 4; j++) acc[t][j] = 0.f;
    float m0 = -1e30f, m1 = -1e30f, l0 = 0.f, l1 = 0.f;

    for (int kt = 0; kt <= qt; kt++) {
        const int k0 = kt * 64;
        __syncthreads();

        // K tile — group A
#pragma unroll
        for (int t = 0; t < 8; t++) {
            int c = tid + t * 128;
            int row = c >> 4;
            int col = (c & 15) * 8;
            size_t g = ((size_t)(b * SEQ + k0 + row)) * KVDIM + kvh * HD + col;
            uint32_t sa = (uint32_t)__cvta_generic_to_shared(sK + row * AT_STR + col);
            asm volatile("cp.async.cg.shared.global [%0], [%1], 16;" :: "r"(sa), "l"(Kp + g));
        }
        asm volatile("cp.async.commit_group;");
        // V tile — group B
#pragma unroll
        for (int t = 0; t < 8; t++) {
            int c = tid + t * 128;
            int row = c >> 4;
            int col = (c & 15) * 8;
            size_t g = ((size_t)(b * SEQ + k0 + row)) * KVDIM + kvh * HD + col;
            uint32_t sa = (uint32_t)__cvta_generic_to_shared(sV + row * AT_STR + col);
            asm volatile("cp.async.cg.shared.global [%0], [%1], 16;" :: "r"(sa), "l"(Vp + g));
        }
        asm volatile("cp.async.commit_group;");

        asm volatile("cp.async.wait_group 1;");
        __syncthreads();

        // S = Q K^T  (Q hi/lo, K plain)
        float S[8][4];
#pragma unroll
        for (int t = 0; t < 8; t++)
#pragma unroll
            for (int j = 0; j < 4; j++) S[t][j] = 0.f;

#pragma unroll
        for (int ks = 0; ks < 8; ks++) {
            uint32_t ah[4], al[4];
            ldmat_x4(ah[0], ah[1], ah[2], ah[3], sQh + (wm + lrow) * AT_STR + ks * 16 + lkof);
            ldmat_x4(al[0], al[1], al[2], al[3], sQl + (wm + lrow) * AT_STR + ks * 16 + lkof);
#pragma unroll
            for (int nh = 0; nh < 4; nh++) {
                uint32_t d0, d1, d2, d3;
                ldmat_x4(d0, d1, d2, d3, sK + (nh * 16 + lrow) * AT_STR + ks * 16 + lkof);
                mma_f16(S[2 * nh], ah, d0, d2);
                mma_f16(S[2 * nh], al, d0, d2);
                mma_f16(S[2 * nh + 1], ah, d1, d3);
                mma_f16(S[2 * nh + 1], al, d1, d3);
            }
        }

        // softcap + mask + online softmax
#pragma unroll
        for (int t = 0; t < 8; t++)
#pragma unroll
            for (int j = 0; j < 4; j++) S[t][j] = softcap50(S[t][j]);

        if (kt == qt) {
            const int r0g = q0 + wm + (lane >> 2);
#pragma unroll
            for (int t = 0; t < 8; t++) {
                int cb = k0 + t * 8 + 2 * (lane & 3);
                if (cb > r0g)         S[t][0] = -30000.f;
                if (cb + 1 > r0g)     S[t][1] = -30000.f;
                if (cb > r0g + 8)     S[t][2] = -30000.f;
                if (cb + 1 > r0g + 8) S[t][3] = -30000.f;
            }
        }

        float mx0 = -1e30f, mx1 = -1e30f;
#pragma unroll
        for (int t = 0; t < 8; t++) {
            mx0 = fmaxf(mx0, fmaxf(S[t][0], S[t][1]));
            mx1 = fmaxf(mx1, fmaxf(S[t][2], S[t][3]));
        }
        mx0 = fmaxf(mx0, __shfl_xor_sync(0xffffffffu, mx0, 1));
        mx0 = fmaxf(mx0, __shfl_xor_sync(0xffffffffu, mx0, 2));
        mx1 = fmaxf(mx1, __shfl_xor_sync(0xffffffffu, mx1, 1));
        mx1 = fmaxf(mx1, __shfl_xor_sync(0xffffffffu, mx1, 2));

        float m0n = fmaxf(m0, mx0);
        float m1n = fmaxf(m1, mx1);
        float corr0 = fexp(m0 - m0n);
        float corr1 = fexp(m1 - m1n);

        float rs0 = 0.f, rs1 = 0.f;
#pragma unroll
        for (int t = 0; t < 8; t++) {
            S[t][0] = fexp(S[t][0] - m0n);
            S[t][1] = fexp(S[t][1] - m0n);
            S[t][2] = fexp(S[t][2] - m1n);
            S[t][3] = fexp(S[t][3] - m1n);
            rs0 += S[t][0] + S[t][1];
            rs1 += S[t][2] + S[t][3];
        }
        rs0 += __shfl_xor_sync(0xffffffffu, rs0, 1);
        rs0 += __shfl_xor_sync(0xffffffffu, rs0, 2);
        rs1 += __shfl_xor_sync(0xffffffffu, rs1, 1);
        rs1 += __shfl_xor_sync(0xffffffffu, rs1, 2);

        l0 = l0 * corr0 + rs0;  m0 = m0n;
        l1 = l1 * corr1 + rs1;  m1 = m1n;

#pragma unroll
        for (int t = 0; t < 16; t++) {
            acc[t][0] *= corr0; acc[t][1] *= corr0;
            acc[t][2] *= corr1; acc[t][3] *= corr1;
        }

        asm volatile("cp.async.wait_group 0;");
        __syncthreads();

        // O += P V  (P split hi/lo in registers, V plain)
#pragma unroll
        for (int pk = 0; pk < 4; pk++) {
            uint32_t ph[4], pl[4];
            float v, hv;
            float hA[8], lA[8];
#pragma unroll
            for (int e = 0; e < 4; e++) {
                v = S[2 * pk][e];     hv = __half2float(__float2half_rn(v));
                hA[e] = hv; lA[e] = v - hv;
                v = S[2 * pk + 1][e]; hv = __half2float(__float2half_rn(v));
                hA[4 + e] = hv; lA[4 + e] = v - hv;
            }
            ph[0] = pack2h(hA[0], hA[1]); ph[1] = pack2h(hA[2], hA[3]);
            ph[2] = pack2h(hA[4], hA[5]); ph[3] = pack2h(hA[6], hA[7]);
            pl[0] = pack2h(lA[0], lA[1]); pl[1] = pack2h(lA[2], lA[3]);
            pl[2] = pack2h(lA[4], lA[5]); pl[3] = pack2h(lA[6], lA[7]);

#pragma unroll
            for (int nh = 0; nh < 8; nh++) {
                uint32_t d0, d1, d2, d3;
                ldmat_x4t(d0, d1, d2, d3, sV + (pk * 16 + lrow) * AT_STR + nh * 16 + lkof);
                mma_f16(acc[2 * nh], ph, d0, d1);
                mma_f16(acc[2 * nh], pl, d0, d1);
                mma_f16(acc[2 * nh + 1], ph, d2, d3);
                mma_f16(acc[2 * nh + 1], pl, d2, d3);
            }
        }
    }

    // epilogue: normalize, split to fp16 hi/lo, store
    float inv0 = 1.0f / l0;
    float inv1 = 1.0f / l1;
    size_t row0 = (size_t)(b * SEQ + q0 + wm + (lane >> 2));
    size_t row1 = row0 + 8;
    int colb = h * HD + 2 * (lane & 3);
#pragma unroll
    for (int t = 0; t < 16; t++) {
        float v0 = acc[t][0] * inv0, v1 = acc[t][1] * inv0;
        float v2 = acc[t][2] * inv1, v3 = acc[t][3] * inv1;
        float h0 = __half2float(__float2half_rn(v0));
        float h1 = __half2float(__float2half_rn(v1));
        float h2 = __half2float(__float2half_rn(v2));
        float h3 = __half2float(__float2half_rn(v3));
        size_t o0 = row0 * QDIM + colb + t * 8;
        size_t o1 = row1 * QDIM + colb + t * 8;
        *(uint32_t*)&Oh[o0] = pack2h(h0, h1);
        *(uint32_t*)&Ol[o0] = pack2h(v0 - h0, v1 - h1);
        *(uint32_t*)&Oh[o1] = pack2h(h2, h3);
        *(uint32_t*)&Ol[o1] = pack2h(v2 - h2, v3 - h3);
    }
}

// ---------------------------------------------------------------------------
extern "C" void kernel_launch(void* const* d_in, const int* in_sizes, int n_in,
                              void* d_out, int out_size)
{
    const float* x  = (const float*)d_in[0];
    const float* wq = (const float*)d_in[1];
    const float* wk = (const float*)d_in[2];
    const float* wv = (const float*)d_in[3];
    const float* wo = (const float*)d_in[4];
    float* out = (float*)d_out;

    float *Qp, *Kp, *Vp, *ropeT;
    cudaGetSymbolAddress((void**)&Qp, g_Q);
    cudaGetSymbolAddress((void**)&Kp, g_K);
    cudaGetSymbolAddress((void**)&Vp, g_V);
    cudaGetSymbolAddress((void**)&ropeT, g_rope);

    __half *xh, *xl, *wq16, *wk16, *wv16, *wo16, *oh, *ol, *qh, *ql, *k16, *v16;
    cudaGetSymbolAddress((void**)&xh, g_xh);     cudaGetSymbolAddress((void**)&xl, g_xl);
    cudaGetSymbolAddress((void**)&wq16, g_wq16); cudaGetSymbolAddress((void**)&wk16, g_wk16);
    cudaGetSymbolAddress((void**)&wv16, g_wv16); cudaGetSymbolAddress((void**)&wo16, g_wo16);
    cudaGetSymbolAddress((void**)&oh, g_oh);     cudaGetSymbolAddress((void**)&ol, g_ol);
    cudaGetSymbolAddress((void**)&qh, g_qh);     cudaGetSymbolAddress((void**)&ql, g_ql);
    cudaGetSymbolAddress((void**)&k16, g_k16);   cudaGetSymbolAddress((void**)&v16, g_v16);

    static bool attrs_set = false;
    static const int GS = 2 * 3 * GTILE * 2;        // 61440 B
    static const int AS = 4 * AT_TILE * 2;          // 69632 B
    if (!attrs_set) {
        cudaFuncSetAttribute(gemm_f16x2, cudaFuncAttributeMaxDynamicSharedMemorySize, GS);
        cudaFuncSetAttribute(attn_f16, cudaFuncAttributeMaxDynamicSharedMemorySize, AS);
        attrs_set = true;
    }

    // 1. operand conversion: x -> fp16 hi/lo; weights -> plain fp16
    {
        int n;
        n = ROWS * DMODEL / 4;
        split4h_kernel<<<(n + 255) / 256, 256>>>((const float4*)x, (__half2*)xh, (__half2*)xl, n);
        n = QDIM * DMODEL / 4;
        cvt4h_kernel<<<(n + 255) / 256, 256>>>((const float4*)wq, (__half2*)wq16, n);
        n = KVDIM * DMODEL / 4;
        cvt4h_kernel<<<(n + 255) / 256, 256>>>((const float4*)wk, (__half2*)wk16, n);
        cvt4h_kernel<<<(n + 255) / 256, 256>>>((const float4*)wv, (__half2*)wv16, n);
        n = DMODEL * QDIM / 4;
        cvt4h_kernel<<<(n + 255) / 256, 256>>>((const float4*)wo, (__half2*)wo16, n);
    }

    // 2. rope table
    rope_table_kernel<<<(SEQ * 64 + 255) / 256, 256>>>(ropeT);

    // 3. QKV projections (fp16x2)
    gemm_f16x2<<<dim3(QDIM / GBN, ROWS / GBM), 256, GS>>>(xh, xl, wq16, Qp, ROWS, QDIM, DMODEL);
    gemm_f16x2<<<dim3(KVDIM / GBN, ROWS / GBM), 256, GS>>>(xh, xl, wk16, Kp, ROWS, KVDIM, DMODEL);
    gemm_f16x2<<<dim3(KVDIM / GBN, ROWS / GBM), 256, GS>>>(xh, xl, wv16, Vp, ROWS, KVDIM, DMODEL);

    // 4. RoPE: Q -> fp16 hi/lo (scale folded); K -> plain fp16; V -> plain fp16
    {
        int totq = ROWS * NHEADS * 64;
        int totk = ROWS * NKV * 64;
        rope_split_kernel<<<(totq + 255) / 256, 256>>>(Qp, ropeT, qh, ql, NHEADS, totq, 0.08838834764831845f);
        rope_cvt_kernel<<<(totk + 255) / 256, 256>>>(Kp, ropeT, k16, NKV, totk);
        int n = ROWS * KVDIM / 4;
        cvt4h_kernel<<<(n + 255) / 256, 256>>>((const float4*)Vp, (__half2*)v16, n);
    }

    // 5. attention (fp16, writes hi/lo output)
    attn_f16<<<dim3(SEQ / 64, NHEADS, BATCH), 128, AS>>>(qh, ql, k16, v16, oh, ol);

    // 6. output projection (fp16x2)
    gemm_f16x2<<<dim3(DMODEL / GBN, ROWS / GBM), 256, GS>>>(oh, ol, wo16, out, ROWS, DMODEL, DMODEL);
}